// round 12
// baseline (speedup 1.0000x reference)
#include <cuda_runtime.h>
#include <cuda_bf16.h>
#include <cuda_fp16.h>
#include <stdint.h>

#define Bn   64
#define Sn   512
#define INn  1024
#define HIDn 1024
#define G4   4096
#define Mtot 32768
#define NCTA 128
#define NTHR 256

// ---- device scratch ----
__device__ __half g_scr[(size_t)Mtot * G4];             // x@U + bias (fp16, 256MB)
__device__ float c_buf[Bn * HIDn];
__device__ int   g_flags[Sn + 1][2][2];                 // [step][group][k-half] counters
__device__ __half u_h[(size_t)G4 * INn];                // U^T [N][K] fp16
__device__ __half vt_h[(size_t)G4 * HIDn];              // V^T [N][K] fp16
__device__ __half hb[2][Bn * HIDn];                     // h carried as fp16

// ---- helpers ----
__device__ __forceinline__ uint32_t smem_u32(const void* p) {
    uint32_t a;
    asm("{ .reg .u64 t; cvta.to.shared.u64 t, %1; cvt.u32.u64 %0, t; }" : "=r"(a) : "l"(p));
    return a;
}
__device__ __forceinline__ void ldsm4(uint32_t r[4], uint32_t addr) {
    asm volatile("ldmatrix.sync.aligned.m8n8.x4.shared.b16 {%0,%1,%2,%3}, [%4];"
        : "=r"(r[0]), "=r"(r[1]), "=r"(r[2]), "=r"(r[3]) : "r"(addr));
}
__device__ __forceinline__ void mma_f16(float c[4], const uint32_t a[4],
                                        uint32_t b0, uint32_t b1) {
    asm volatile("mma.sync.aligned.m16n8k16.row.col.f32.f16.f16.f32 "
        "{%0,%1,%2,%3}, {%4,%5,%6,%7}, {%8,%9}, {%0,%1,%2,%3};"
        : "+f"(c[0]), "+f"(c[1]), "+f"(c[2]), "+f"(c[3])
        : "r"(a[0]), "r"(a[1]), "r"(a[2]), "r"(a[3]), "r"(b0), "r"(b1));
}
__device__ __forceinline__ float tanh_f(float x) {
    float y;
    asm("tanh.approx.f32 %0, %1;" : "=f"(y) : "f"(x));
    return y;
}
__device__ __forceinline__ float sigmoid_f(float x) {
    return fmaf(0.5f, tanh_f(0.5f * x), 0.5f);
}

// ---------------------------------------------------------------------------
// Merged prep: U^T fp16, V^T fp16, state init, flag init.
__global__ void conv_uv_init_k(const float* __restrict__ U,
                               const float* __restrict__ V,
                               const float* __restrict__ h0,
                               const float* __restrict__ c0) {
    size_t i = (size_t)blockIdx.x * blockDim.x + threadIdx.x;
    const size_t NU = (size_t)G4 * INn;
    if (i < NU) {
        size_t n = i / INn, k = i % INn;
        u_h[i] = __float2half_rn(U[k * G4 + n]);
    } else if (i < 2 * NU) {
        size_t j = i - NU;
        size_t n = j / HIDn, k = j % HIDn;
        vt_h[j] = __float2half_rn(V[k * G4 + n]);
    }
    if (i < Bn * HIDn) {
        c_buf[i] = c0[i];
        hb[0][i] = __float2half_rn(h0[i]);
    }
    if (i < (Sn + 1) * 4) ((int*)g_flags)[i] = (i < 4) ? 32 : 0;
}

// ---------------------------------------------------------------------------
// Phase 1: single-plane fp16 HMMA GEMM; epilogue stores fp16 g_scr.
// ---------------------------------------------------------------------------
#define SA   80
#define TAB  (128 * SA)
#define CHB  (2 * TAB)
#define SM1  (2 * CHB)

#define P1_LOADA(kc) do { \
    _Pragma("unroll") \
    for (int i = 0; i < 4; ++i) { \
        int e = tid + i * 256; int rr = e >> 3; int kq = e & 7; \
        pfA[i] = *(const float4*)(x + (size_t)(m0 + rr) * INn + (kc) * 32 + kq * 4); \
    } } while (0)
#define P1_LOADB(kc) do { \
    _Pragma("unroll") \
    for (int i = 0; i < 2; ++i) { \
        int e = tid + i * 256; int rr = e >> 2; int c = e & 3; \
        pfB[i] = *(const float4*)(u_h + (size_t)(n0 + rr) * INn + (kc) * 32 + c * 8); \
    } } while (0)
#define P1_STORE(b) do { \
    _Pragma("unroll") \
    for (int i = 0; i < 4; ++i) { \
        int e = tid + i * 256; int rr = e >> 3; int kq = e & 7; \
        __half2 h01 = __floats2half2_rn(pfA[i].x, pfA[i].y); \
        __half2 h23 = __floats2half2_rn(pfA[i].z, pfA[i].w); \
        uint2 wv; wv.x = *(uint32_t*)&h01; wv.y = *(uint32_t*)&h23; \
        *(uint2*)(sm + (b) * CHB + rr * SA + kq * 8) = wv; \
    } \
    _Pragma("unroll") \
    for (int i = 0; i < 2; ++i) { \
        int e = tid + i * 256; int rr = e >> 2; int c = e & 3; \
        *(float4*)(sm + (b) * CHB + TAB + rr * SA + c * 16) = pfB[i]; \
    } } while (0)

__global__ __launch_bounds__(256, 1) void gemm_xu_mma(const float* __restrict__ x,
                                                      const float* __restrict__ bias) {
    extern __shared__ char sm[];
    const uint32_t smb = smem_u32(sm);
    const int tid = threadIdx.x, w = tid >> 5, l = tid & 31;
    const int m0 = blockIdx.y * 128, n0 = blockIdx.x * 128;
    const int wm = w >> 1, wn = w & 1;
    const int gr = l >> 2, q = l & 3;
    const int rA = (l & 7) + ((l >> 3) & 1) * 8, cA = (l >> 4) * 16;
    const int rB = (l & 7) + ((l >> 4) & 1) * 8, cB = ((l >> 3) & 1) * 16;

    float acc[2][8][4];
#pragma unroll
    for (int a = 0; a < 2; ++a)
#pragma unroll
        for (int b = 0; b < 8; ++b)
#pragma unroll
            for (int c = 0; c < 4; ++c) acc[a][b][c] = 0.0f;

    float4 pfA[4], pfB[2];
    P1_LOADA(0);
    P1_LOADB(0);
    P1_STORE(0);
    P1_LOADA(1);
    P1_LOADB(1);
    __syncthreads();

    for (int kc = 0; kc < 32; ++kc) {
        const int buf = kc & 1;
        if (kc + 1 < 32) P1_STORE(buf ^ 1);
        if (kc + 2 < 32) { P1_LOADA(kc + 2); P1_LOADB(kc + 2); }

        const uint32_t base = smb + buf * CHB;
#pragma unroll
        for (int ks = 0; ks < 2; ++ks) {
            uint32_t ah[2][4];
#pragma unroll
            for (int mfi = 0; mfi < 2; ++mfi) {
                uint32_t ra = base + (uint32_t)((wm * 32 + mfi * 16 + rA) * SA + ks * 32 + cA);
                ldsm4(ah[mfi], ra);
            }
#pragma unroll
            for (int np = 0; np < 4; ++np) {
                uint32_t rb = base + TAB +
                              (uint32_t)((wn * 64 + np * 16 + rB) * SA + ks * 32 + cB);
                uint32_t bh[4];
                ldsm4(bh, rb);
#pragma unroll
                for (int mfi = 0; mfi < 2; ++mfi) {
                    mma_f16(acc[mfi][2 * np],     ah[mfi], bh[0], bh[1]);
                    mma_f16(acc[mfi][2 * np + 1], ah[mfi], bh[2], bh[3]);
                }
            }
        }
        __syncthreads();
    }

#pragma unroll
    for (int mfi = 0; mfi < 2; ++mfi) {
#pragma unroll
        for (int nf = 0; nf < 8; ++nf) {
            int row = m0 + wm * 32 + mfi * 16 + gr;
            int col = n0 + wn * 64 + nf * 8 + 2 * q;
            float2 bz = *(const float2*)(bias + col);
            *(__half2*)(g_scr + (size_t)row * G4 + col) =
                __floats2half2_rn(acc[mfi][nf][0] + bz.x, acc[mfi][nf][1] + bz.y);
            *(__half2*)(g_scr + (size_t)(row + 8) * G4 + col) =
                __floats2half2_rn(acc[mfi][nf][2] + bz.x, acc[mfi][nf][3] + bz.y);
        }
    }
}

// ---------------------------------------------------------------------------
// Phase 2: batch-split persistent recurrence.
//  - per-(group,k-half) flags: 32 producers each; chunk-0 load starts as soon
//    as its producers finish (overlaps chunk-1 producer tail)
//  - continuous lane-0 polling (no nanosleep quantization)
//  - fp16 g_scr reads; tail (h_fin/c_fin) written in-kernel at t=Sn-1
// ---------------------------------------------------------------------------
#define KP2    2064
#define HB_OFF (64 * KP2)
#define HROW   1040
#define HBUF   (32 * HROW)
#define GSM_O  (HB_OFF + 2 * HBUF)
#define SM2    (GSM_O + 32 * 68 * 4)

#define POLL_FLAG(pt, pc) do { \
    if (l == 0) { \
        const int* _fp = &g_flags[(pt)][gid][(pc)]; \
        int _v; \
        do { \
            asm volatile("ld.acquire.gpu.global.s32 %0, [%1];" : "=r"(_v) : "l"(_fp) : "memory"); \
        } while (_v < 32); \
    } \
    __syncwarp(); } while (0)

#define P2_ISSUE(ch) do { \
    _Pragma("unroll") \
    for (int i = 0; i < 8; ++i) { \
        int e = tid + i * 256; int rr = e >> 6; int c16 = e & 63; \
        uint32_t dst = smb + HB_OFF + (ch) * HBUF + rr * HROW + c16 * 16; \
        const __half* src = hh + (size_t)rr * HIDn + (ch) * 512 + c16 * 8; \
        asm volatile("cp.async.cg.shared.global [%0], [%1], 16;" :: "r"(dst), "l"(src) : "memory"); \
    } \
    asm volatile("cp.async.commit_group;" ::: "memory"); } while (0)

#define P2_COMPUTE(ch) do { \
    const uint32_t ab = smb + HB_OFF + (ch) * HBUF + (uint32_t)((mf * 16 + rA) * HROW + cA); \
    const uint32_t bb = smb + (uint32_t)((nb + rB) * KP2 + (ch) * 1024 + cB); \
    _Pragma("unroll") \
    for (int ks = 0; ks < 32; ++ks) { \
        uint32_t a4[4], b4[4]; \
        ldsm4(a4, ab + ks * 32); \
        ldsm4(b4, bb + ks * 32); \
        mma_f16(acc[0], a4, b4[0], b4[1]); \
        mma_f16(acc[1], a4, b4[2], b4[3]); \
    } } while (0)

__global__ __launch_bounds__(NTHR, 1) void lstm_persist_mma(float* __restrict__ out,
                                                            float* __restrict__ out_tail) {
    extern __shared__ char sm[];
    const uint32_t smb = smem_u32(sm);
    float* gsm = (float*)(sm + GSM_O);
    const int tid = threadIdx.x, w = tid >> 5, l = tid & 31;
    const int gid   = blockIdx.x & 1;
    const int cid   = blockIdx.x >> 1;
    const int j0    = cid * 16;
    const int rbase = gid * 32;
    const int myhalf = cid >> 5;             // which k-half this CTA's h cols feed
    const int mf = w >> 2, nb = (w & 3) * 16;
    const int gr = l >> 2, q = l & 3;
    const int rA = (l & 7) + ((l >> 3) & 1) * 8, cA = (l >> 4) * 16;
    const int rB = (l & 7) + ((l >> 4) & 1) * 8, cB = ((l >> 3) & 1) * 16;

    // Load V^T slice (64 gate-cols x 1024 k, fp16) once: 128KB.
#pragma unroll
    for (int i = 0; i < 32; ++i) {
        int e = tid + i * 256;
        int r = e >> 7, c = e & 127;
        int gv = (r >> 4) * 1024 + j0 + (r & 15);
        *(float4*)(sm + r * KP2 + c * 16) = *(const float4*)(vt_h + (size_t)gv * HIDn + c * 8);
    }
    __syncthreads();

    for (int t = 0; t < Sn; ++t) {
        const __half* hh  = hb[t & 1] + (size_t)rbase * HIDn;
        const int     nxt = (t & 1) ^ 1;

        // Prefetch x@U+bias (fp16; independent of flags, overlaps poll).
        float2 gpre[4];
        {
            int m = rbase + mf * 16 + gr;
            const __half* gp = g_scr + ((size_t)(m * Sn + t)) * G4;
#pragma unroll
            for (int nf = 0; nf < 2; ++nf) {
                int c = nb + nf * 8 + 2 * q;
                int gcol = (c >> 4) * HIDn + j0 + (c & 15);
                gpre[nf * 2]     = __half22float2(*(const __half2*)(gp + gcol));
                gpre[nf * 2 + 1] = __half22float2(*(const __half2*)(gp + (size_t)8 * Sn * G4 + gcol));
            }
        }

        float acc[2][4];
#pragma unroll
        for (int a = 0; a < 2; ++a)
#pragma unroll
            for (int c = 0; c < 4; ++c) acc[a][c] = 0.0f;

        POLL_FLAG(t, 0);
        P2_ISSUE(0);
        POLL_FLAG(t, 1);
        P2_ISSUE(1);

        asm volatile("cp.async.wait_group 1;" ::: "memory");
        __syncthreads();
        P2_COMPUTE(0);
        asm volatile("cp.async.wait_group 0;" ::: "memory");
        __syncthreads();
        P2_COMPUTE(1);

        // Stage pre-activations into gsm [32 rows][64 gate-cols, stride 68].
#pragma unroll
        for (int nf = 0; nf < 2; ++nf) {
            int m = mf * 16 + gr;
            int c = nb + nf * 8 + 2 * q;
            gsm[m * 68 + c]           = acc[nf][0] + gpre[nf * 2].x;
            gsm[m * 68 + c + 1]       = acc[nf][1] + gpre[nf * 2].y;
            gsm[(m + 8) * 68 + c]     = acc[nf][2] + gpre[nf * 2 + 1].x;
            gsm[(m + 8) * 68 + c + 1] = acc[nf][3] + gpre[nf * 2 + 1].y;
        }
        __syncthreads();

        // Gates: 32 rows x 16 h-cols = 512 cells, 2 per thread.
        float cnr[2], hnr[2];
        int   idxr[2];
#pragma unroll
        for (int p = 0; p < 2; ++p) {
            int e  = tid + p * 256;
            int m  = e >> 4;
            int jj = e & 15;
            float gn = gsm[m * 68 + jj];
            float gi = gsm[m * 68 + 16 + jj];
            float gf = gsm[m * 68 + 32 + jj];
            float go = gsm[m * 68 + 48 + jj];
            float nv = tanh_f(gn);
            float iv = sigmoid_f(gi);
            float fv = sigmoid_f(gf);
            float ov = sigmoid_f(go);
            int idx = (rbase + m) * HIDn + j0 + jj;
            float cn = c_buf[idx] * fv + nv * iv;
            float hn = tanh_f(cn) * ov;
            hb[nxt][idx] = __float2half_rn(hn);
            cnr[p] = cn; hnr[p] = hn; idxr[p] = idx;
        }

        // Publish: this CTA's h cols for step t+1 are ready (group,k-half flag).
        __syncthreads();
        if (tid == 0) {
            const int* fp = &g_flags[t + 1][gid][myhalf];
            asm volatile("red.release.gpu.global.add.s32 [%0], %1;"
                         :: "l"(fp), "r"(1) : "memory");
        }

        // Deferred stores (off the inter-CTA critical path).
#pragma unroll
        for (int p = 0; p < 2; ++p) {
            int e  = tid + p * 256;
            int m  = e >> 4;
            int jj = e & 15;
            c_buf[idxr[p]] = cnr[p];
            out[((size_t)(rbase + m) * Sn + t) * HIDn + j0 + jj] = hnr[p];
            if (t == Sn - 1 && out_tail) {
                out_tail[idxr[p]]             = hnr[p];
                out_tail[Bn * HIDn + idxr[p]] = cnr[p];
            }
        }
    }
}

extern "C" void kernel_launch(void* const* d_in, const int* in_sizes, int n_in,
                              void* d_out, int out_size) {
    const float* x    = (const float*)d_in[0];
    const float* U    = (const float*)d_in[1];
    const float* V    = (const float*)d_in[2];
    const float* bias = (const float*)d_in[3];
    const float* h0   = (const float*)d_in[4];
    const float* c0   = (const float*)d_in[5];
    float* out = (float*)d_out;

    static int attr_done = 0;
    if (!attr_done) {
        cudaFuncSetAttribute(gemm_xu_mma,
                             cudaFuncAttributeMaxDynamicSharedMemorySize, SM1);
        cudaFuncSetAttribute(lstm_persist_mma,
                             cudaFuncAttributeMaxDynamicSharedMemorySize, SM2);
        attr_done = 1;
    }

    conv_uv_init_k<<<(int)((2 * (size_t)G4 * INn + 255) / 256), 256>>>(U, V, h0, c0);

    dim3 gg(G4 / 128, Mtot / 128);
    gemm_xu_mma<<<gg, 256, SM1>>>(x, bias);

    long long main_elems = (long long)Bn * Sn * HIDn;
    float* tail = ((long long)out_size >= main_elems + 2LL * Bn * HIDn)
                  ? (out + main_elems) : nullptr;
    lstm_persist_mma<<<NCTA, NTHR, SM2>>>(out, tail);
}

// round 13
// speedup vs baseline: 1.0733x; 1.0733x over previous
#include <cuda_runtime.h>
#include <cuda_bf16.h>
#include <cuda_fp16.h>
#include <stdint.h>

#define Bn   64
#define Sn   512
#define INn  1024
#define HIDn 1024
#define G4   4096
#define Mtot 32768
#define NCTA 128
#define NTHR 256

// ---- device scratch ----
__device__ __half g_scr[(size_t)Mtot * G4];             // x@U + bias (fp16, 256MB)
__device__ float c_buf[Bn * HIDn];
__device__ int   g_flags[Sn + 1][2];                    // [step][group] counters
__device__ __half u_h[(size_t)G4 * INn];                // U^T [N][K] fp16
__device__ __half vt_h[(size_t)G4 * HIDn];              // V^T [N][K] fp16
__device__ __half hb[2][Bn * HIDn];                     // h carried as fp16

// ---- helpers ----
__device__ __forceinline__ uint32_t smem_u32(const void* p) {
    uint32_t a;
    asm("{ .reg .u64 t; cvta.to.shared.u64 t, %1; cvt.u32.u64 %0, t; }" : "=r"(a) : "l"(p));
    return a;
}
__device__ __forceinline__ void ldsm4(uint32_t r[4], uint32_t addr) {
    asm volatile("ldmatrix.sync.aligned.m8n8.x4.shared.b16 {%0,%1,%2,%3}, [%4];"
        : "=r"(r[0]), "=r"(r[1]), "=r"(r[2]), "=r"(r[3]) : "r"(addr));
}
__device__ __forceinline__ void mma_f16(float c[4], const uint32_t a[4],
                                        uint32_t b0, uint32_t b1) {
    asm volatile("mma.sync.aligned.m16n8k16.row.col.f32.f16.f16.f32 "
        "{%0,%1,%2,%3}, {%4,%5,%6,%7}, {%8,%9}, {%0,%1,%2,%3};"
        : "+f"(c[0]), "+f"(c[1]), "+f"(c[2]), "+f"(c[3])
        : "r"(a[0]), "r"(a[1]), "r"(a[2]), "r"(a[3]), "r"(b0), "r"(b1));
}
__device__ __forceinline__ float tanh_f(float x) {
    float y;
    asm("tanh.approx.f32 %0, %1;" : "=f"(y) : "f"(x));
    return y;
}
__device__ __forceinline__ float sigmoid_f(float x) {
    return fmaf(0.5f, tanh_f(0.5f * x), 0.5f);
}

// ---------------------------------------------------------------------------
// Merged prep: U^T fp16, V^T fp16, state init, flag init.
__global__ void conv_uv_init_k(const float* __restrict__ U,
                               const float* __restrict__ V,
                               const float* __restrict__ h0,
                               const float* __restrict__ c0) {
    size_t i = (size_t)blockIdx.x * blockDim.x + threadIdx.x;
    const size_t NU = (size_t)G4 * INn;
    if (i < NU) {
        size_t n = i / INn, k = i % INn;
        u_h[i] = __float2half_rn(U[k * G4 + n]);
    } else if (i < 2 * NU) {
        size_t j = i - NU;
        size_t n = j / HIDn, k = j % HIDn;
        vt_h[j] = __float2half_rn(V[k * G4 + n]);
    }
    if (i < Bn * HIDn) {
        c_buf[i] = c0[i];
        hb[0][i] = __float2half_rn(h0[i]);
    }
    if (i < (Sn + 1) * 2) ((int*)g_flags)[i] = (i < 2) ? 64 : 0;
}

// ---------------------------------------------------------------------------
// Phase 1: single-plane fp16 HMMA GEMM; epilogue stores fp16 g_scr.
// ---------------------------------------------------------------------------
#define SA   80
#define TAB  (128 * SA)
#define CHB  (2 * TAB)
#define SM1  (2 * CHB)

#define P1_LOADA(kc) do { \
    _Pragma("unroll") \
    for (int i = 0; i < 4; ++i) { \
        int e = tid + i * 256; int rr = e >> 3; int kq = e & 7; \
        pfA[i] = *(const float4*)(x + (size_t)(m0 + rr) * INn + (kc) * 32 + kq * 4); \
    } } while (0)
#define P1_LOADB(kc) do { \
    _Pragma("unroll") \
    for (int i = 0; i < 2; ++i) { \
        int e = tid + i * 256; int rr = e >> 2; int c = e & 3; \
        pfB[i] = *(const float4*)(u_h + (size_t)(n0 + rr) * INn + (kc) * 32 + c * 8); \
    } } while (0)
#define P1_STORE(b) do { \
    _Pragma("unroll") \
    for (int i = 0; i < 4; ++i) { \
        int e = tid + i * 256; int rr = e >> 3; int kq = e & 7; \
        __half2 h01 = __floats2half2_rn(pfA[i].x, pfA[i].y); \
        __half2 h23 = __floats2half2_rn(pfA[i].z, pfA[i].w); \
        uint2 wv; wv.x = *(uint32_t*)&h01; wv.y = *(uint32_t*)&h23; \
        *(uint2*)(sm + (b) * CHB + rr * SA + kq * 8) = wv; \
    } \
    _Pragma("unroll") \
    for (int i = 0; i < 2; ++i) { \
        int e = tid + i * 256; int rr = e >> 2; int c = e & 3; \
        *(float4*)(sm + (b) * CHB + TAB + rr * SA + c * 16) = pfB[i]; \
    } } while (0)

__global__ __launch_bounds__(256, 1) void gemm_xu_mma(const float* __restrict__ x,
                                                      const float* __restrict__ bias) {
    extern __shared__ char sm[];
    const uint32_t smb = smem_u32(sm);
    const int tid = threadIdx.x, w = tid >> 5, l = tid & 31;
    const int m0 = blockIdx.y * 128, n0 = blockIdx.x * 128;
    const int wm = w >> 1, wn = w & 1;
    const int gr = l >> 2, q = l & 3;
    const int rA = (l & 7) + ((l >> 3) & 1) * 8, cA = (l >> 4) * 16;
    const int rB = (l & 7) + ((l >> 4) & 1) * 8, cB = ((l >> 3) & 1) * 16;

    float acc[2][8][4];
#pragma unroll
    for (int a = 0; a < 2; ++a)
#pragma unroll
        for (int b = 0; b < 8; ++b)
#pragma unroll
            for (int c = 0; c < 4; ++c) acc[a][b][c] = 0.0f;

    float4 pfA[4], pfB[2];
    P1_LOADA(0);
    P1_LOADB(0);
    P1_STORE(0);
    P1_LOADA(1);
    P1_LOADB(1);
    __syncthreads();

    for (int kc = 0; kc < 32; ++kc) {
        const int buf = kc & 1;
        if (kc + 1 < 32) P1_STORE(buf ^ 1);
        if (kc + 2 < 32) { P1_LOADA(kc + 2); P1_LOADB(kc + 2); }

        const uint32_t base = smb + buf * CHB;
#pragma unroll
        for (int ks = 0; ks < 2; ++ks) {
            uint32_t ah[2][4];
#pragma unroll
            for (int mfi = 0; mfi < 2; ++mfi) {
                uint32_t ra = base + (uint32_t)((wm * 32 + mfi * 16 + rA) * SA + ks * 32 + cA);
                ldsm4(ah[mfi], ra);
            }
#pragma unroll
            for (int np = 0; np < 4; ++np) {
                uint32_t rb = base + TAB +
                              (uint32_t)((wn * 64 + np * 16 + rB) * SA + ks * 32 + cB);
                uint32_t bh[4];
                ldsm4(bh, rb);
#pragma unroll
                for (int mfi = 0; mfi < 2; ++mfi) {
                    mma_f16(acc[mfi][2 * np],     ah[mfi], bh[0], bh[1]);
                    mma_f16(acc[mfi][2 * np + 1], ah[mfi], bh[2], bh[3]);
                }
            }
        }
        __syncthreads();
    }

#pragma unroll
    for (int mfi = 0; mfi < 2; ++mfi) {
#pragma unroll
        for (int nf = 0; nf < 8; ++nf) {
            int row = m0 + wm * 32 + mfi * 16 + gr;
            int col = n0 + wn * 64 + nf * 8 + 2 * q;
            float2 bz = *(const float2*)(bias + col);
            *(__half2*)(g_scr + (size_t)row * G4 + col) =
                __floats2half2_rn(acc[mfi][nf][0] + bz.x, acc[mfi][nf][1] + bz.y);
            *(__half2*)(g_scr + (size_t)(row + 8) * G4 + col) =
                __floats2half2_rn(acc[mfi][nf][2] + bz.x, acc[mfi][nf][3] + bz.y);
        }
    }
}

// ---------------------------------------------------------------------------
// Phase 2: batch-split persistent recurrence (R11 sync protocol — single
// per-group flag + nanosleep backoff; known good). fp16 g_scr reads;
// tail (h_fin/c_fin) fused at t=Sn-1.
// ---------------------------------------------------------------------------
#define KP2    2064
#define HB_OFF (64 * KP2)
#define HROW   1040
#define HBUF   (32 * HROW)
#define GSM_O  (HB_OFF + 2 * HBUF)
#define SM2    (GSM_O + 32 * 68 * 4)

#define POLL_FLAG(pt) do { \
    if (l == 0) { \
        const int* _fp = &g_flags[(pt)][gid]; \
        int _v, _sp = 0; \
        for (;;) { \
            asm volatile("ld.acquire.gpu.global.s32 %0, [%1];" : "=r"(_v) : "l"(_fp) : "memory"); \
            if (_v >= 64) break; \
            if (++_sp > 16) { __nanosleep(64); _sp = 0; } \
        } \
    } \
    __syncwarp(); } while (0)

#define P2_ISSUE(ch) do { \
    _Pragma("unroll") \
    for (int i = 0; i < 8; ++i) { \
        int e = tid + i * 256; int rr = e >> 6; int c16 = e & 63; \
        uint32_t dst = smb + HB_OFF + (ch) * HBUF + rr * HROW + c16 * 16; \
        const __half* src = hh + (size_t)rr * HIDn + (ch) * 512 + c16 * 8; \
        asm volatile("cp.async.cg.shared.global [%0], [%1], 16;" :: "r"(dst), "l"(src) : "memory"); \
    } \
    asm volatile("cp.async.commit_group;" ::: "memory"); } while (0)

#define P2_COMPUTE(ch) do { \
    const uint32_t ab = smb + HB_OFF + (ch) * HBUF + (uint32_t)((mf * 16 + rA) * HROW + cA); \
    const uint32_t bb = smb + (uint32_t)((nb + rB) * KP2 + (ch) * 1024 + cB); \
    _Pragma("unroll") \
    for (int ks = 0; ks < 32; ++ks) { \
        uint32_t a4[4], b4[4]; \
        ldsm4(a4, ab + ks * 32); \
        ldsm4(b4, bb + ks * 32); \
        mma_f16(acc[0], a4, b4[0], b4[1]); \
        mma_f16(acc[1], a4, b4[2], b4[3]); \
    } } while (0)

__global__ __launch_bounds__(NTHR, 1) void lstm_persist_mma(float* __restrict__ out,
                                                            float* __restrict__ out_tail) {
    extern __shared__ char sm[];
    const uint32_t smb = smem_u32(sm);
    float* gsm = (float*)(sm + GSM_O);
    const int tid = threadIdx.x, w = tid >> 5, l = tid & 31;
    const int gid   = blockIdx.x & 1;
    const int cid   = blockIdx.x >> 1;
    const int j0    = cid * 16;
    const int rbase = gid * 32;
    const int mf = w >> 2, nb = (w & 3) * 16;
    const int gr = l >> 2, q = l & 3;
    const int rA = (l & 7) + ((l >> 3) & 1) * 8, cA = (l >> 4) * 16;
    const int rB = (l & 7) + ((l >> 4) & 1) * 8, cB = ((l >> 3) & 1) * 16;

    // Load V^T slice (64 gate-cols x 1024 k, fp16) once: 128KB.
#pragma unroll
    for (int i = 0; i < 32; ++i) {
        int e = tid + i * 256;
        int r = e >> 7, c = e & 127;
        int gv = (r >> 4) * 1024 + j0 + (r & 15);
        *(float4*)(sm + r * KP2 + c * 16) = *(const float4*)(vt_h + (size_t)gv * HIDn + c * 8);
    }
    __syncthreads();

    for (int t = 0; t < Sn; ++t) {
        const __half* hh  = hb[t & 1] + (size_t)rbase * HIDn;
        const int     nxt = (t & 1) ^ 1;

        // Prefetch x@U+bias (fp16; independent of flags, overlaps poll).
        float2 gpre[4];
        {
            int m = rbase + mf * 16 + gr;
            const __half* gp = g_scr + ((size_t)(m * Sn + t)) * G4;
#pragma unroll
            for (int nf = 0; nf < 2; ++nf) {
                int c = nb + nf * 8 + 2 * q;
                int gcol = (c >> 4) * HIDn + j0 + (c & 15);
                gpre[nf * 2]     = __half22float2(*(const __half2*)(gp + gcol));
                gpre[nf * 2 + 1] = __half22float2(*(const __half2*)(gp + (size_t)8 * Sn * G4 + gcol));
            }
        }

        float acc[2][4];
#pragma unroll
        for (int a = 0; a < 2; ++a)
#pragma unroll
            for (int c = 0; c < 4; ++c) acc[a][c] = 0.0f;

        POLL_FLAG(t);
        P2_ISSUE(0);
        P2_ISSUE(1);

        asm volatile("cp.async.wait_group 1;" ::: "memory");
        __syncthreads();
        P2_COMPUTE(0);
        asm volatile("cp.async.wait_group 0;" ::: "memory");
        __syncthreads();
        P2_COMPUTE(1);

        // Stage pre-activations into gsm [32 rows][64 gate-cols, stride 68].
#pragma unroll
        for (int nf = 0; nf < 2; ++nf) {
            int m = mf * 16 + gr;
            int c = nb + nf * 8 + 2 * q;
            gsm[m * 68 + c]           = acc[nf][0] + gpre[nf * 2].x;
            gsm[m * 68 + c + 1]       = acc[nf][1] + gpre[nf * 2].y;
            gsm[(m + 8) * 68 + c]     = acc[nf][2] + gpre[nf * 2 + 1].x;
            gsm[(m + 8) * 68 + c + 1] = acc[nf][3] + gpre[nf * 2 + 1].y;
        }
        __syncthreads();

        // Gates: 32 rows x 16 h-cols = 512 cells, 2 per thread.
        float cnr[2], hnr[2];
        int   idxr[2];
#pragma unroll
        for (int p = 0; p < 2; ++p) {
            int e  = tid + p * 256;
            int m  = e >> 4;
            int jj = e & 15;
            float gn = gsm[m * 68 + jj];
            float gi = gsm[m * 68 + 16 + jj];
            float gf = gsm[m * 68 + 32 + jj];
            float go = gsm[m * 68 + 48 + jj];
            float nv = tanh_f(gn);
            float iv = sigmoid_f(gi);
            float fv = sigmoid_f(gf);
            float ov = sigmoid_f(go);
            int idx = (rbase + m) * HIDn + j0 + jj;
            float cn = c_buf[idx] * fv + nv * iv;
            float hn = tanh_f(cn) * ov;
            hb[nxt][idx] = __float2half_rn(hn);
            cnr[p] = cn; hnr[p] = hn; idxr[p] = idx;
        }

        // Publish: this CTA's h cols for step t+1 are ready (group flag).
        __syncthreads();
        if (tid == 0) {
            const int* fp = &g_flags[t + 1][gid];
            asm volatile("red.release.gpu.global.add.s32 [%0], %1;"
                         :: "l"(fp), "r"(1) : "memory");
        }

        // Deferred stores (off the inter-CTA critical path).
#pragma unroll
        for (int p = 0; p < 2; ++p) {
            int e  = tid + p * 256;
            int m  = e >> 4;
            int jj = e & 15;
            c_buf[idxr[p]] = cnr[p];
            out[((size_t)(rbase + m) * Sn + t) * HIDn + j0 + jj] = hnr[p];
            if (t == Sn - 1 && out_tail) {
                out_tail[idxr[p]]             = hnr[p];
                out_tail[Bn * HIDn + idxr[p]] = cnr[p];
            }
        }
    }
}

extern "C" void kernel_launch(void* const* d_in, const int* in_sizes, int n_in,
                              void* d_out, int out_size) {
    const float* x    = (const float*)d_in[0];
    const float* U    = (const float*)d_in[1];
    const float* V    = (const float*)d_in[2];
    const float* bias = (const float*)d_in[3];
    const float* h0   = (const float*)d_in[4];
    const float* c0   = (const float*)d_in[5];
    float* out = (float*)d_out;

    static int attr_done = 0;
    if (!attr_done) {
        cudaFuncSetAttribute(gemm_xu_mma,
                             cudaFuncAttributeMaxDynamicSharedMemorySize, SM1);
        cudaFuncSetAttribute(lstm_persist_mma,
                             cudaFuncAttributeMaxDynamicSharedMemorySize, SM2);
        attr_done = 1;
    }

    conv_uv_init_k<<<(int)((2 * (size_t)G4 * INn + 255) / 256), 256>>>(U, V, h0, c0);

    dim3 gg(G4 / 128, Mtot / 128);
    gemm_xu_mma<<<gg, 256, SM1>>>(x, bias);

    long long main_elems = (long long)Bn * Sn * HIDn;
    float* tail = ((long long)out_size >= main_elems + 2LL * Bn * HIDn)
                  ? (out + main_elems) : nullptr;
    lstm_persist_mma<<<NCTA, NTHR, SM2>>>(out, tail);
}

// round 14
// speedup vs baseline: 1.0951x; 1.0203x over previous
#include <cuda_runtime.h>
#include <cuda_bf16.h>
#include <cuda_fp16.h>
#include <stdint.h>

#define Bn   64
#define Sn   512
#define INn  1024
#define HIDn 1024
#define G4   4096
#define Mtot 32768
#define NCTA 128
#define NTHR 256

// ---- device scratch ----
__device__ __half g_scr[(size_t)Mtot * G4];             // x@U + bias (fp16, 256MB)
__device__ float c_buf[Bn * HIDn];
__device__ int   g_flags[Sn + 1][2];                    // [step][group] counters
__device__ __half u_h[(size_t)G4 * INn];                // U^T [N][K] fp16
__device__ __half vt_h[(size_t)G4 * HIDn];              // V^T [N][K] fp16
// h carry: [buf][group][kchunk][32 rows][512 cols], swizzled 16B chunks,
// each (buf,group,kchunk) block is 32KB CONTIGUOUS for cp.async.bulk.
__device__ __half hb2[2][2][2][32 * 512];

// ---- helpers ----
__device__ __forceinline__ uint32_t smem_u32(const void* p) {
    uint32_t a;
    asm("{ .reg .u64 t; cvta.to.shared.u64 t, %1; cvt.u32.u64 %0, t; }" : "=r"(a) : "l"(p));
    return a;
}
__device__ __forceinline__ void ldsm4(uint32_t r[4], uint32_t addr) {
    asm volatile("ldmatrix.sync.aligned.m8n8.x4.shared.b16 {%0,%1,%2,%3}, [%4];"
        : "=r"(r[0]), "=r"(r[1]), "=r"(r[2]), "=r"(r[3]) : "r"(addr));
}
__device__ __forceinline__ void mma_f16(float c[4], const uint32_t a[4],
                                        uint32_t b0, uint32_t b1) {
    asm volatile("mma.sync.aligned.m16n8k16.row.col.f32.f16.f16.f32 "
        "{%0,%1,%2,%3}, {%4,%5,%6,%7}, {%8,%9}, {%0,%1,%2,%3};"
        : "+f"(c[0]), "+f"(c[1]), "+f"(c[2]), "+f"(c[3])
        : "r"(a[0]), "r"(a[1]), "r"(a[2]), "r"(a[3]), "r"(b0), "r"(b1));
}
__device__ __forceinline__ float tanh_f(float x) {
    float y;
    asm("tanh.approx.f32 %0, %1;" : "=f"(y) : "f"(x));
    return y;
}
__device__ __forceinline__ float sigmoid_f(float x) {
    return fmaf(0.5f, tanh_f(0.5f * x), 0.5f);
}
// swizzled position of (row r in 0..31, col cc in 0..511) inside a 32x512 chunk
__device__ __forceinline__ int hswz(int r, int cc) {
    return r * 512 + ((((cc >> 3) ^ (r & 7)) << 3) | (cc & 7));
}

#define MBAR_INIT(a, c) asm volatile("mbarrier.init.shared.b64 [%0], %1;" :: "r"(a), "r"(c) : "memory")
#define MBAR_EXPECT_TX(a, b) asm volatile("mbarrier.arrive.expect_tx.shared.b64 _, [%0], %1;" :: "r"(a), "r"(b) : "memory")
#define MBAR_WAIT(a, ph) do { \
    uint32_t _m = (a), _p = (ph), _d; \
    asm volatile("{ .reg .pred p; mbarrier.try_wait.parity.acquire.cta.shared::cta.b64 p, [%1], %2; selp.b32 %0,1,0,p; }" \
        : "=r"(_d) : "r"(_m), "r"(_p) : "memory"); \
    if (!_d) { \
        asm volatile("{ .reg .pred P1; WL_%=: mbarrier.try_wait.parity.acquire.cta.shared::cta.b64 P1, [%0], %1, 0x989680; @P1 bra.uni WD_%=; bra.uni WL_%=; WD_%=: }" \
            :: "r"(_m), "r"(_p) : "memory"); \
    } } while (0)
#define BULK_LD(dst, src, bytes, mbar) \
    asm volatile("cp.async.bulk.shared::cluster.global.mbarrier::complete_tx::bytes [%0], [%1], %2, [%3];" \
        :: "r"(dst), "l"(src), "r"(bytes), "r"(mbar) : "memory")

// ---------------------------------------------------------------------------
// Merged prep: U^T fp16, V^T fp16, state init (h0 swizzled into hb2), flags.
__global__ void conv_uv_init_k(const float* __restrict__ U,
                               const float* __restrict__ V,
                               const float* __restrict__ h0,
                               const float* __restrict__ c0) {
    size_t i = (size_t)blockIdx.x * blockDim.x + threadIdx.x;
    const size_t NU = (size_t)G4 * INn;
    if (i < NU) {
        size_t n = i / INn, k = i % INn;
        u_h[i] = __float2half_rn(U[k * G4 + n]);
    } else if (i < 2 * NU) {
        size_t j = i - NU;
        size_t n = j / HIDn, k = j % HIDn;
        vt_h[j] = __float2half_rn(V[k * G4 + n]);
    }
    if (i < Bn * HIDn) {
        c_buf[i] = c0[i];
        int r = (int)(i >> 10), j = (int)(i & 1023);
        int gid = r >> 5, rr = r & 31, kc = j >> 9, cc = j & 511;
        hb2[0][gid][kc][hswz(rr, cc)] = __float2half_rn(h0[i]);
    }
    if (i < (Sn + 1) * 2) ((int*)g_flags)[i] = (i < 2) ? 64 : 0;
}

// ---------------------------------------------------------------------------
// Phase 1: single-plane fp16 HMMA GEMM; epilogue stores fp16 g_scr. (R13)
// ---------------------------------------------------------------------------
#define SA   80
#define TAB  (128 * SA)
#define CHB  (2 * TAB)
#define SM1  (2 * CHB)

#define P1_LOADA(kc) do { \
    _Pragma("unroll") \
    for (int i = 0; i < 4; ++i) { \
        int e = tid + i * 256; int rr = e >> 3; int kq = e & 7; \
        pfA[i] = *(const float4*)(x + (size_t)(m0 + rr) * INn + (kc) * 32 + kq * 4); \
    } } while (0)
#define P1_LOADB(kc) do { \
    _Pragma("unroll") \
    for (int i = 0; i < 2; ++i) { \
        int e = tid + i * 256; int rr = e >> 2; int c = e & 3; \
        pfB[i] = *(const float4*)(u_h + (size_t)(n0 + rr) * INn + (kc) * 32 + c * 8); \
    } } while (0)
#define P1_STORE(b) do { \
    _Pragma("unroll") \
    for (int i = 0; i < 4; ++i) { \
        int e = tid + i * 256; int rr = e >> 3; int kq = e & 7; \
        __half2 h01 = __floats2half2_rn(pfA[i].x, pfA[i].y); \
        __half2 h23 = __floats2half2_rn(pfA[i].z, pfA[i].w); \
        uint2 wv; wv.x = *(uint32_t*)&h01; wv.y = *(uint32_t*)&h23; \
        *(uint2*)(sm + (b) * CHB + rr * SA + kq * 8) = wv; \
    } \
    _Pragma("unroll") \
    for (int i = 0; i < 2; ++i) { \
        int e = tid + i * 256; int rr = e >> 2; int c = e & 3; \
        *(float4*)(sm + (b) * CHB + TAB + rr * SA + c * 16) = pfB[i]; \
    } } while (0)

__global__ __launch_bounds__(256, 1) void gemm_xu_mma(const float* __restrict__ x,
                                                      const float* __restrict__ bias) {
    extern __shared__ char sm[];
    const uint32_t smb = smem_u32(sm);
    const int tid = threadIdx.x, w = tid >> 5, l = tid & 31;
    const int m0 = blockIdx.y * 128, n0 = blockIdx.x * 128;
    const int wm = w >> 1, wn = w & 1;
    const int gr = l >> 2, q = l & 3;
    const int rA = (l & 7) + ((l >> 3) & 1) * 8, cA = (l >> 4) * 16;
    const int rB = (l & 7) + ((l >> 4) & 1) * 8, cB = ((l >> 3) & 1) * 16;

    float acc[2][8][4];
#pragma unroll
    for (int a = 0; a < 2; ++a)
#pragma unroll
        for (int b = 0; b < 8; ++b)
#pragma unroll
            for (int c = 0; c < 4; ++c) acc[a][b][c] = 0.0f;

    float4 pfA[4], pfB[2];
    P1_LOADA(0);
    P1_LOADB(0);
    P1_STORE(0);
    P1_LOADA(1);
    P1_LOADB(1);
    __syncthreads();

    for (int kc = 0; kc < 32; ++kc) {
        const int buf = kc & 1;
        if (kc + 1 < 32) P1_STORE(buf ^ 1);
        if (kc + 2 < 32) { P1_LOADA(kc + 2); P1_LOADB(kc + 2); }

        const uint32_t base = smb + buf * CHB;
#pragma unroll
        for (int ks = 0; ks < 2; ++ks) {
            uint32_t ah[2][4];
#pragma unroll
            for (int mfi = 0; mfi < 2; ++mfi) {
                uint32_t ra = base + (uint32_t)((wm * 32 + mfi * 16 + rA) * SA + ks * 32 + cA);
                ldsm4(ah[mfi], ra);
            }
#pragma unroll
            for (int np = 0; np < 4; ++np) {
                uint32_t rb = base + TAB +
                              (uint32_t)((wn * 64 + np * 16 + rB) * SA + ks * 32 + cB);
                uint32_t bh[4];
                ldsm4(bh, rb);
#pragma unroll
                for (int mfi = 0; mfi < 2; ++mfi) {
                    mma_f16(acc[mfi][2 * np],     ah[mfi], bh[0], bh[1]);
                    mma_f16(acc[mfi][2 * np + 1], ah[mfi], bh[2], bh[3]);
                }
            }
        }
        __syncthreads();
    }

#pragma unroll
    for (int mfi = 0; mfi < 2; ++mfi) {
#pragma unroll
        for (int nf = 0; nf < 8; ++nf) {
            int row = m0 + wm * 32 + mfi * 16 + gr;
            int col = n0 + wn * 64 + nf * 8 + 2 * q;
            float2 bz = *(const float2*)(bias + col);
            *(__half2*)(g_scr + (size_t)row * G4 + col) =
                __floats2half2_rn(acc[mfi][nf][0] + bz.x, acc[mfi][nf][1] + bz.y);
            *(__half2*)(g_scr + (size_t)(row + 8) * G4 + col) =
                __floats2half2_rn(acc[mfi][nf][2] + bz.x, acc[mfi][nf][3] + bz.y);
        }
    }
}

// ---------------------------------------------------------------------------
// Phase 2: batch-split persistent recurrence with BULK h ingest.
//  - h chunk = contiguous 32KB in hb2; ONE cp.async.bulk per chunk (tid 0),
//    mbarrier complete_tx; only tid 0 polls the group flag.
//  - smem h buffers linear (1024B rows) with XOR(row&7) 16B-chunk swizzle.
// ---------------------------------------------------------------------------
#define KP2    2064
#define HB_OFF (64 * KP2)                 // 132096
#define HCHK   32768                      // bytes per h chunk in smem
#define GSM_O  (HB_OFF + 2 * HCHK)        // 197632
#define MB_OFF (GSM_O + 32 * 68 * 4)      // 206336
#define SM2    (MB_OFF + 16)

#define P2_COMPUTE(ch) do { \
    const uint32_t bb = smb + (uint32_t)((nb + rB) * KP2 + (ch) * 1024 + cB); \
    _Pragma("unroll") \
    for (int ks = 0; ks < 32; ++ks) { \
        uint32_t a4[4], b4[4]; \
        ldsm4(a4, abase + (ch) * HCHK + (uint32_t)(((((ks << 1) | aoff) ^ axor) << 4))); \
        ldsm4(b4, bb + ks * 32); \
        mma_f16(acc[0], a4, b4[0], b4[1]); \
        mma_f16(acc[1], a4, b4[2], b4[3]); \
    } } while (0)

__global__ __launch_bounds__(NTHR, 1) void lstm_persist_mma(float* __restrict__ out,
                                                            float* __restrict__ out_tail) {
    extern __shared__ char sm[];
    const uint32_t smb = smem_u32(sm);
    float* gsm = (float*)(sm + GSM_O);
    const uint32_t mb0 = smb + MB_OFF, mb1 = smb + MB_OFF + 8;
    const int tid = threadIdx.x, w = tid >> 5, l = tid & 31;
    const int gid   = blockIdx.x & 1;
    const int cid   = blockIdx.x >> 1;
    const int j0    = cid * 16;
    const int rbase = gid * 32;
    const int mf = w >> 2, nb = (w & 3) * 16;
    const int gr = l >> 2, q = l & 3;
    const int rA = (l & 7) + ((l >> 3) & 1) * 8, cA = (l >> 4) * 16;
    const int rB = (l & 7) + ((l >> 4) & 1) * 8, cB = ((l >> 3) & 1) * 16;

    // A-ldsm swizzled addressing (row-fixed per lane)
    const int arow  = mf * 16 + rA;                    // 0..31
    const uint32_t abase = smb + HB_OFF + (uint32_t)(arow * 1024);
    const int axor  = arow & 7;
    const int aoff  = cA >> 4;                         // 0 or 1

    // Producer h-write constants
    const int kc_mine  = j0 >> 9;                      // which k-chunk this CTA feeds
    const int cc3base  = (j0 & 511) >> 3;

    if (tid == 0) { MBAR_INIT(mb0, 1); MBAR_INIT(mb1, 1); }

    // Load V^T slice (64 gate-cols x 1024 k, fp16) once: 128KB.
#pragma unroll
    for (int i = 0; i < 32; ++i) {
        int e = tid + i * 256;
        int r = e >> 7, c = e & 127;
        int gv = (r >> 4) * 1024 + j0 + (r & 15);
        *(float4*)(sm + r * KP2 + c * 16) = *(const float4*)(vt_h + (size_t)gv * HIDn + c * 8);
    }
    __syncthreads();

    int ph = 0;
    for (int t = 0; t < Sn; ++t) {
        const int buf = t & 1, nxt = buf ^ 1;

        // Prefetch x@U+bias (fp16; independent of flags).
        float2 gpre[4];
        {
            int m = rbase + mf * 16 + gr;
            const __half* gp = g_scr + ((size_t)(m * Sn + t)) * G4;
#pragma unroll
            for (int nf = 0; nf < 2; ++nf) {
                int c = nb + nf * 8 + 2 * q;
                int gcol = (c >> 4) * HIDn + j0 + (c & 15);
                gpre[nf * 2]     = __half22float2(*(const __half2*)(gp + gcol));
                gpre[nf * 2 + 1] = __half22float2(*(const __half2*)(gp + (size_t)8 * Sn * G4 + gcol));
            }
        }

        float acc[2][4];
#pragma unroll
        for (int a = 0; a < 2; ++a)
#pragma unroll
            for (int c = 0; c < 4; ++c) acc[a][c] = 0.0f;

        // tid 0: poll flag, then DMA both chunks.
        if (tid == 0) {
            const int* fp = &g_flags[t][gid];
            int v, sp = 0;
            for (;;) {
                asm volatile("ld.acquire.gpu.global.s32 %0, [%1];" : "=r"(v) : "l"(fp) : "memory");
                if (v >= 64) break;
                if (++sp > 16) { __nanosleep(64); sp = 0; }
            }
            MBAR_EXPECT_TX(mb0, HCHK);
            BULK_LD(smb + HB_OFF, (const void*)&hb2[buf][gid][0][0], HCHK, mb0);
            MBAR_EXPECT_TX(mb1, HCHK);
            BULK_LD(smb + HB_OFF + HCHK, (const void*)&hb2[buf][gid][1][0], HCHK, mb1);
        }

        MBAR_WAIT(mb0, ph);
        P2_COMPUTE(0);
        MBAR_WAIT(mb1, ph);
        P2_COMPUTE(1);
        ph ^= 1;

        // Stage pre-activations into gsm [32 rows][64 gate-cols, stride 68].
#pragma unroll
        for (int nf = 0; nf < 2; ++nf) {
            int m = mf * 16 + gr;
            int c = nb + nf * 8 + 2 * q;
            gsm[m * 68 + c]           = acc[nf][0] + gpre[nf * 2].x;
            gsm[m * 68 + c + 1]       = acc[nf][1] + gpre[nf * 2].y;
            gsm[(m + 8) * 68 + c]     = acc[nf][2] + gpre[nf * 2 + 1].x;
            gsm[(m + 8) * 68 + c + 1] = acc[nf][3] + gpre[nf * 2 + 1].y;
        }
        __syncthreads();

        // Gates: 32 rows x 16 h-cols = 512 cells, 2 per thread.
        float cnr[2], hnr[2];
        int   idxr[2];
#pragma unroll
        for (int p = 0; p < 2; ++p) {
            int e  = tid + p * 256;
            int m  = e >> 4;
            int jj = e & 15;
            float gn = gsm[m * 68 + jj];
            float gi = gsm[m * 68 + 16 + jj];
            float gf = gsm[m * 68 + 32 + jj];
            float go = gsm[m * 68 + 48 + jj];
            float nv = tanh_f(gn);
            float iv = sigmoid_f(gi);
            float fv = sigmoid_f(gf);
            float ov = sigmoid_f(go);
            int idx = (rbase + m) * HIDn + j0 + jj;
            float cn = c_buf[idx] * fv + nv * iv;
            float hn = tanh_f(cn) * ov;
            // swizzled h store into next buffer's chunk
            int pos = m * 512 + (((cc3base + (jj >> 3)) ^ (m & 7)) << 3) + (jj & 7);
            hb2[nxt][gid][kc_mine][pos] = __float2half_rn(hn);
            cnr[p] = cn; hnr[p] = hn; idxr[p] = idx;
        }

        // Publish: this CTA's h cols for step t+1 are ready (group flag).
        __syncthreads();
        if (tid == 0) {
            const int* fp = &g_flags[t + 1][gid];
            asm volatile("red.release.gpu.global.add.s32 [%0], %1;"
                         :: "l"(fp), "r"(1) : "memory");
        }

        // Deferred stores (off the inter-CTA critical path).
#pragma unroll
        for (int p = 0; p < 2; ++p) {
            int e  = tid + p * 256;
            int m  = e >> 4;
            int jj = e & 15;
            c_buf[idxr[p]] = cnr[p];
            out[((size_t)(rbase + m) * Sn + t) * HIDn + j0 + jj] = hnr[p];
            if (t == Sn - 1 && out_tail) {
                out_tail[idxr[p]]             = hnr[p];
                out_tail[Bn * HIDn + idxr[p]] = cnr[p];
            }
        }
    }
}

extern "C" void kernel_launch(void* const* d_in, const int* in_sizes, int n_in,
                              void* d_out, int out_size) {
    const float* x    = (const float*)d_in[0];
    const float* U    = (const float*)d_in[1];
    const float* V    = (const float*)d_in[2];
    const float* bias = (const float*)d_in[3];
    const float* h0   = (const float*)d_in[4];
    const float* c0   = (const float*)d_in[5];
    float* out = (float*)d_out;

    static int attr_done = 0;
    if (!attr_done) {
        cudaFuncSetAttribute(gemm_xu_mma,
                             cudaFuncAttributeMaxDynamicSharedMemorySize, SM1);
        cudaFuncSetAttribute(lstm_persist_mma,
                             cudaFuncAttributeMaxDynamicSharedMemorySize, SM2);
        attr_done = 1;
    }

    conv_uv_init_k<<<(int)((2 * (size_t)G4 * INn + 255) / 256), 256>>>(U, V, h0, c0);

    dim3 gg(G4 / 128, Mtot / 128);
    gemm_xu_mma<<<gg, 256, SM1>>>(x, bias);

    long long main_elems = (long long)Bn * Sn * HIDn;
    float* tail = ((long long)out_size >= main_elems + 2LL * Bn * HIDn)
                  ? (out + main_elems) : nullptr;
    lstm_persist_mma<<<NCTA, NTHR, SM2>>>(out, tail);
}

// round 15
// speedup vs baseline: 1.1348x; 1.0362x over previous
#include <cuda_runtime.h>
#include <cuda_bf16.h>
#include <cuda_fp16.h>
#include <stdint.h>

#define Bn   64
#define Sn   512
#define INn  1024
#define HIDn 1024
#define G4   4096
#define Mtot 32768
#define NCTA 128
#define NTHR 256

// ---- device scratch ----
__device__ __half g_scr[(size_t)Mtot * G4];             // x@U + bias (fp16, 256MB)
__device__ float c_buf[Bn * HIDn];
__device__ int   g_flags[Sn + 1][2][2];                 // [step][group][k-half]
__device__ __half u_h[(size_t)G4 * INn];                // U^T [N][K] fp16
__device__ __half vt_h[(size_t)G4 * HIDn];              // V^T [N][K] fp16
// h carry: [buf][group][kchunk][32 rows][512 cols], swizzled 16B chunks,
// each (buf,group,kchunk) block is 32KB CONTIGUOUS for cp.async.bulk.
__device__ __half hb2[2][2][2][32 * 512];

// ---- helpers ----
__device__ __forceinline__ uint32_t smem_u32(const void* p) {
    uint32_t a;
    asm("{ .reg .u64 t; cvta.to.shared.u64 t, %1; cvt.u32.u64 %0, t; }" : "=r"(a) : "l"(p));
    return a;
}
__device__ __forceinline__ void ldsm4(uint32_t r[4], uint32_t addr) {
    asm volatile("ldmatrix.sync.aligned.m8n8.x4.shared.b16 {%0,%1,%2,%3}, [%4];"
        : "=r"(r[0]), "=r"(r[1]), "=r"(r[2]), "=r"(r[3]) : "r"(addr));
}
__device__ __forceinline__ void mma_f16(float c[4], const uint32_t a[4],
                                        uint32_t b0, uint32_t b1) {
    asm volatile("mma.sync.aligned.m16n8k16.row.col.f32.f16.f16.f32 "
        "{%0,%1,%2,%3}, {%4,%5,%6,%7}, {%8,%9}, {%0,%1,%2,%3};"
        : "+f"(c[0]), "+f"(c[1]), "+f"(c[2]), "+f"(c[3])
        : "r"(a[0]), "r"(a[1]), "r"(a[2]), "r"(a[3]), "r"(b0), "r"(b1));
}
__device__ __forceinline__ float tanh_f(float x) {
    float y;
    asm("tanh.approx.f32 %0, %1;" : "=f"(y) : "f"(x));
    return y;
}
__device__ __forceinline__ float sigmoid_f(float x) {
    return fmaf(0.5f, tanh_f(0.5f * x), 0.5f);
}
__device__ __forceinline__ int hswz(int r, int cc) {
    return r * 512 + ((((cc >> 3) ^ (r & 7)) << 3) | (cc & 7));
}

#define MBAR_INIT(a, c) asm volatile("mbarrier.init.shared.b64 [%0], %1;" :: "r"(a), "r"(c) : "memory")
#define MBAR_EXPECT_TX(a, b) asm volatile("mbarrier.arrive.expect_tx.shared.b64 _, [%0], %1;" :: "r"(a), "r"(b) : "memory")
#define MBAR_WAIT(a, ph) do { \
    uint32_t _m = (a), _p = (ph), _d; \
    asm volatile("{ .reg .pred p; mbarrier.try_wait.parity.acquire.cta.shared::cta.b64 p, [%1], %2; selp.b32 %0,1,0,p; }" \
        : "=r"(_d) : "r"(_m), "r"(_p) : "memory"); \
    if (!_d) { \
        asm volatile("{ .reg .pred P1; WL_%=: mbarrier.try_wait.parity.acquire.cta.shared::cta.b64 P1, [%0], %1, 0x989680; @P1 bra.uni WD_%=; bra.uni WL_%=; WD_%=: }" \
            :: "r"(_m), "r"(_p) : "memory"); \
    } } while (0)
#define BULK_LD(dst, src, bytes, mbar) \
    asm volatile("cp.async.bulk.shared::cluster.global.mbarrier::complete_tx::bytes [%0], [%1], %2, [%3];" \
        :: "r"(dst), "l"(src), "r"(bytes), "r"(mbar) : "memory")

// tid-0 poll (backoff) then DMA one 32KB chunk
#define POLL_AND_DMA(pt, half, mb) do { \
    const int* _fp = &g_flags[(pt)][gid][(half)]; \
    int _v, _sp = 0; \
    for (;;) { \
        asm volatile("ld.acquire.gpu.global.s32 %0, [%1];" : "=r"(_v) : "l"(_fp) : "memory"); \
        if (_v >= 32) break; \
        if (++_sp > 16) { __nanosleep(64); _sp = 0; } \
    } \
    MBAR_EXPECT_TX((mb), HCHK); \
    BULK_LD(smb + HB_OFF + (half) * HCHK, \
            (const void*)&hb2[(pt) & 1][gid][(half)][0], HCHK, (mb)); \
} while (0)

// ---------------------------------------------------------------------------
// Merged prep: U^T fp16, V^T fp16, state init (h0 swizzled into hb2), flags.
__global__ void conv_uv_init_k(const float* __restrict__ U,
                               const float* __restrict__ V,
                               const float* __restrict__ h0,
                               const float* __restrict__ c0) {
    size_t i = (size_t)blockIdx.x * blockDim.x + threadIdx.x;
    const size_t NU = (size_t)G4 * INn;
    if (i < NU) {
        size_t n = i / INn, k = i % INn;
        u_h[i] = __float2half_rn(U[k * G4 + n]);
    } else if (i < 2 * NU) {
        size_t j = i - NU;
        size_t n = j / HIDn, k = j % HIDn;
        vt_h[j] = __float2half_rn(V[k * G4 + n]);
    }
    if (i < Bn * HIDn) {
        c_buf[i] = c0[i];
        int r = (int)(i >> 10), j = (int)(i & 1023);
        int gid = r >> 5, rr = r & 31, kc = j >> 9, cc = j & 511;
        hb2[0][gid][kc][hswz(rr, cc)] = __float2half_rn(h0[i]);
    }
    if (i < (Sn + 1) * 4) ((int*)g_flags)[i] = (i < 4) ? 32 : 0;
}

// ---------------------------------------------------------------------------
// Phase 1: single-plane fp16 HMMA GEMM; epilogue stores fp16 g_scr. (R13)
// ---------------------------------------------------------------------------
#define SA   80
#define TAB  (128 * SA)
#define CHB  (2 * TAB)
#define SM1  (2 * CHB)

#define P1_LOADA(kc) do { \
    _Pragma("unroll") \
    for (int i = 0; i < 4; ++i) { \
        int e = tid + i * 256; int rr = e >> 3; int kq = e & 7; \
        pfA[i] = *(const float4*)(x + (size_t)(m0 + rr) * INn + (kc) * 32 + kq * 4); \
    } } while (0)
#define P1_LOADB(kc) do { \
    _Pragma("unroll") \
    for (int i = 0; i < 2; ++i) { \
        int e = tid + i * 256; int rr = e >> 2; int c = e & 3; \
        pfB[i] = *(const float4*)(u_h + (size_t)(n0 + rr) * INn + (kc) * 32 + c * 8); \
    } } while (0)
#define P1_STORE(b) do { \
    _Pragma("unroll") \
    for (int i = 0; i < 4; ++i) { \
        int e = tid + i * 256; int rr = e >> 3; int kq = e & 7; \
        __half2 h01 = __floats2half2_rn(pfA[i].x, pfA[i].y); \
        __half2 h23 = __floats2half2_rn(pfA[i].z, pfA[i].w); \
        uint2 wv; wv.x = *(uint32_t*)&h01; wv.y = *(uint32_t*)&h23; \
        *(uint2*)(sm + (b) * CHB + rr * SA + kq * 8) = wv; \
    } \
    _Pragma("unroll") \
    for (int i = 0; i < 2; ++i) { \
        int e = tid + i * 256; int rr = e >> 2; int c = e & 3; \
        *(float4*)(sm + (b) * CHB + TAB + rr * SA + c * 16) = pfB[i]; \
    } } while (0)

__global__ __launch_bounds__(256, 1) void gemm_xu_mma(const float* __restrict__ x,
                                                      const float* __restrict__ bias) {
    extern __shared__ char sm[];
    const uint32_t smb = smem_u32(sm);
    const int tid = threadIdx.x, w = tid >> 5, l = tid & 31;
    const int m0 = blockIdx.y * 128, n0 = blockIdx.x * 128;
    const int wm = w >> 1, wn = w & 1;
    const int gr = l >> 2, q = l & 3;
    const int rA = (l & 7) + ((l >> 3) & 1) * 8, cA = (l >> 4) * 16;
    const int rB = (l & 7) + ((l >> 4) & 1) * 8, cB = ((l >> 3) & 1) * 16;

    float acc[2][8][4];
#pragma unroll
    for (int a = 0; a < 2; ++a)
#pragma unroll
        for (int b = 0; b < 8; ++b)
#pragma unroll
            for (int c = 0; c < 4; ++c) acc[a][b][c] = 0.0f;

    float4 pfA[4], pfB[2];
    P1_LOADA(0);
    P1_LOADB(0);
    P1_STORE(0);
    P1_LOADA(1);
    P1_LOADB(1);
    __syncthreads();

    for (int kc = 0; kc < 32; ++kc) {
        const int buf = kc & 1;
        if (kc + 1 < 32) P1_STORE(buf ^ 1);
        if (kc + 2 < 32) { P1_LOADA(kc + 2); P1_LOADB(kc + 2); }

        const uint32_t base = smb + buf * CHB;
#pragma unroll
        for (int ks = 0; ks < 2; ++ks) {
            uint32_t ah[2][4];
#pragma unroll
            for (int mfi = 0; mfi < 2; ++mfi) {
                uint32_t ra = base + (uint32_t)((wm * 32 + mfi * 16 + rA) * SA + ks * 32 + cA);
                ldsm4(ah[mfi], ra);
            }
#pragma unroll
            for (int np = 0; np < 4; ++np) {
                uint32_t rb = base + TAB +
                              (uint32_t)((wn * 64 + np * 16 + rB) * SA + ks * 32 + cB);
                uint32_t bh[4];
                ldsm4(bh, rb);
#pragma unroll
                for (int mfi = 0; mfi < 2; ++mfi) {
                    mma_f16(acc[mfi][2 * np],     ah[mfi], bh[0], bh[1]);
                    mma_f16(acc[mfi][2 * np + 1], ah[mfi], bh[2], bh[3]);
                }
            }
        }
        __syncthreads();
    }

#pragma unroll
    for (int mfi = 0; mfi < 2; ++mfi) {
#pragma unroll
        for (int nf = 0; nf < 8; ++nf) {
            int row = m0 + wm * 32 + mfi * 16 + gr;
            int col = n0 + wn * 64 + nf * 8 + 2 * q;
            float2 bz = *(const float2*)(bias + col);
            *(__half2*)(g_scr + (size_t)row * G4 + col) =
                __floats2half2_rn(acc[mfi][nf][0] + bz.x, acc[mfi][nf][1] + bz.y);
            *(__half2*)(g_scr + (size_t)(row + 8) * G4 + col) =
                __floats2half2_rn(acc[mfi][nf][2] + bz.x, acc[mfi][nf][3] + bz.y);
        }
    }
}

// ---------------------------------------------------------------------------
// Phase 2: batch-split persistent recurrence, bulk h ingest, HOISTED handoff:
//  - per-(group,k-half) flags (32 producers); tid-0-only backoff polling
//  - next step's poll+DMA issued at END of current step (after own release),
//    overlapping deferred stores / gpre prefetch — loop top just MBAR_WAITs.
// ---------------------------------------------------------------------------
#define KP2    2064
#define HB_OFF (64 * KP2)                 // 132096
#define HCHK   32768
#define GSM_O  (HB_OFF + 2 * HCHK)        // 197632
#define MB_OFF (GSM_O + 32 * 68 * 4)      // 206336
#define SM2    (MB_OFF + 16)

#define P2_COMPUTE(ch) do { \
    const uint32_t bb = smb + (uint32_t)((nb + rB) * KP2 + (ch) * 1024 + cB); \
    _Pragma("unroll") \
    for (int ks = 0; ks < 32; ++ks) { \
        uint32_t a4[4], b4[4]; \
        ldsm4(a4, abase + (ch) * HCHK + (uint32_t)(((((ks << 1) | aoff) ^ axor) << 4))); \
        ldsm4(b4, bb + ks * 32); \
        mma_f16(acc[0], a4, b4[0], b4[1]); \
        mma_f16(acc[1], a4, b4[2], b4[3]); \
    } } while (0)

__global__ __launch_bounds__(NTHR, 1) void lstm_persist_mma(float* __restrict__ out,
                                                            float* __restrict__ out_tail) {
    extern __shared__ char sm[];
    const uint32_t smb = smem_u32(sm);
    float* gsm = (float*)(sm + GSM_O);
    const uint32_t mb0 = smb + MB_OFF, mb1 = smb + MB_OFF + 8;
    const int tid = threadIdx.x, w = tid >> 5, l = tid & 31;
    const int gid   = blockIdx.x & 1;
    const int cid   = blockIdx.x >> 1;
    const int j0    = cid * 16;
    const int rbase = gid * 32;
    const int mf = w >> 2, nb = (w & 3) * 16;
    const int gr = l >> 2, q = l & 3;
    const int rA = (l & 7) + ((l >> 3) & 1) * 8, cA = (l >> 4) * 16;
    const int rB = (l & 7) + ((l >> 4) & 1) * 8, cB = ((l >> 3) & 1) * 16;

    const int arow  = mf * 16 + rA;
    const uint32_t abase = smb + HB_OFF + (uint32_t)(arow * 1024);
    const int axor  = arow & 7;
    const int aoff  = cA >> 4;

    const int kc_mine  = j0 >> 9;
    const int cc3base  = (j0 & 511) >> 3;

    if (tid == 0) { MBAR_INIT(mb0, 1); MBAR_INIT(mb1, 1); }

    // Load V^T slice (64 gate-cols x 1024 k, fp16) once: 128KB.
#pragma unroll
    for (int i = 0; i < 32; ++i) {
        int e = tid + i * 256;
        int r = e >> 7, c = e & 127;
        int gv = (r >> 4) * 1024 + j0 + (r & 15);
        *(float4*)(sm + r * KP2 + c * 16) = *(const float4*)(vt_h + (size_t)gv * HIDn + c * 8);
    }
    __syncthreads();

    // Prologue: issue step 0's DMAs.
    if (tid == 0) {
        POLL_AND_DMA(0, 0, mb0);
        POLL_AND_DMA(0, 1, mb1);
    }

    int ph = 0;
    for (int t = 0; t < Sn; ++t) {
        // Prefetch x@U+bias (fp16; independent of h arrival).
        float2 gpre[4];
        {
            int m = rbase + mf * 16 + gr;
            const __half* gp = g_scr + ((size_t)(m * Sn + t)) * G4;
#pragma unroll
            for (int nf = 0; nf < 2; ++nf) {
                int c = nb + nf * 8 + 2 * q;
                int gcol = (c >> 4) * HIDn + j0 + (c & 15);
                gpre[nf * 2]     = __half22float2(*(const __half2*)(gp + gcol));
                gpre[nf * 2 + 1] = __half22float2(*(const __half2*)(gp + (size_t)8 * Sn * G4 + gcol));
            }
        }

        float acc[2][4];
#pragma unroll
        for (int a = 0; a < 2; ++a)
#pragma unroll
            for (int c = 0; c < 4; ++c) acc[a][c] = 0.0f;

        MBAR_WAIT(mb0, ph);
        P2_COMPUTE(0);
        MBAR_WAIT(mb1, ph);
        P2_COMPUTE(1);
        ph ^= 1;

        // Stage pre-activations into gsm [32 rows][64 gate-cols, stride 68].
#pragma unroll
        for (int nf = 0; nf < 2; ++nf) {
            int m = mf * 16 + gr;
            int c = nb + nf * 8 + 2 * q;
            gsm[m * 68 + c]           = acc[nf][0] + gpre[nf * 2].x;
            gsm[m * 68 + c + 1]       = acc[nf][1] + gpre[nf * 2].y;
            gsm[(m + 8) * 68 + c]     = acc[nf][2] + gpre[nf * 2 + 1].x;
            gsm[(m + 8) * 68 + c + 1] = acc[nf][3] + gpre[nf * 2 + 1].y;
        }
        __syncthreads();

        // Gates: 32 rows x 16 h-cols = 512 cells, 2 per thread.
        const int nxt = (t & 1) ^ 1;
        float cnr[2], hnr[2];
        int   idxr[2];
#pragma unroll
        for (int p = 0; p < 2; ++p) {
            int e  = tid + p * 256;
            int m  = e >> 4;
            int jj = e & 15;
            float gn = gsm[m * 68 + jj];
            float gi = gsm[m * 68 + 16 + jj];
            float gf = gsm[m * 68 + 32 + jj];
            float go = gsm[m * 68 + 48 + jj];
            float nv = tanh_f(gn);
            float iv = sigmoid_f(gi);
            float fv = sigmoid_f(gf);
            float ov = sigmoid_f(go);
            int idx = (rbase + m) * HIDn + j0 + jj;
            float cn = c_buf[idx] * fv + nv * iv;
            float hn = tanh_f(cn) * ov;
            int pos = m * 512 + (((cc3base + (jj >> 3)) ^ (m & 7)) << 3) + (jj & 7);
            hb2[nxt][gid][kc_mine][pos] = __float2half_rn(hn);
            cnr[p] = cn; hnr[p] = hn; idxr[p] = idx;
        }

        // Publish own columns, then HOIST next step's poll+DMA here (overlaps
        // deferred stores and next gpre prefetch). h smem buffers are free.
        __syncthreads();
        if (tid == 0) {
            const int* fp = &g_flags[t + 1][gid][kc_mine];
            asm volatile("red.release.gpu.global.add.s32 [%0], %1;"
                         :: "l"(fp), "r"(1) : "memory");
            if (t + 1 < Sn) {
                POLL_AND_DMA(t + 1, 0, mb0);
                POLL_AND_DMA(t + 1, 1, mb1);
            }
        }

        // Deferred stores (off the inter-CTA critical path).
#pragma unroll
        for (int p = 0; p < 2; ++p) {
            int e  = tid + p * 256;
            int m  = e >> 4;
            int jj = e & 15;
            c_buf[idxr[p]] = cnr[p];
            out[((size_t)(rbase + m) * Sn + t) * HIDn + j0 + jj] = hnr[p];
            if (t == Sn - 1 && out_tail) {
                out_tail[idxr[p]]             = hnr[p];
                out_tail[Bn * HIDn + idxr[p]] = cnr[p];
            }
        }
    }
}

extern "C" void kernel_launch(void* const* d_in, const int* in_sizes, int n_in,
                              void* d_out, int out_size) {
    const float* x    = (const float*)d_in[0];
    const float* U    = (const float*)d_in[1];
    const float* V    = (const float*)d_in[2];
    const float* bias = (const float*)d_in[3];
    const float* h0   = (const float*)d_in[4];
    const float* c0   = (const float*)d_in[5];
    float* out = (float*)d_out;

    static int attr_done = 0;
    if (!attr_done) {
        cudaFuncSetAttribute(gemm_xu_mma,
                             cudaFuncAttributeMaxDynamicSharedMemorySize, SM1);
        cudaFuncSetAttribute(lstm_persist_mma,
                             cudaFuncAttributeMaxDynamicSharedMemorySize, SM2);
        attr_done = 1;
    }

    conv_uv_init_k<<<(int)((2 * (size_t)G4 * INn + 255) / 256), 256>>>(U, V, h0, c0);

    dim3 gg(G4 / 128, Mtot / 128);
    gemm_xu_mma<<<gg, 256, SM1>>>(x, bias);

    long long main_elems = (long long)Bn * Sn * HIDn;
    float* tail = ((long long)out_size >= main_elems + 2LL * Bn * HIDn)
                  ? (out + main_elems) : nullptr;
    lstm_persist_mma<<<NCTA, NTHR, SM2>>>(out, tail);
}